// round 10
// baseline (speedup 1.0000x reference)
#include <cuda_runtime.h>
#include <cuda_fp16.h>
#include <cstdint>

typedef unsigned long long u64;
typedef uint32_t u32;

#define NB 4096
#define NE 16
#define ND 512
#define NH 2048

#define KC 64                          // k-chunk: 64 fp16 = 128B rows
#define XTILE 16384                    // 128 x 64 fp16
#define WTILE 8192                     // 64 x 64 fp16
#define STAGE (XTILE + WTILE)          // 24576
#define NSTAGE 4
#define OFF_STAGES 4096                // after d-table (16*64 floats)
#define SMEM_TOTAL (OFF_STAGES + NSTAGE * STAGE)   // 102400 B -> occupancy 2

// ---------------- scratch (device globals; no allocations allowed) ----------
__device__ __half g_xh[NB * ND];
__device__ __half g_wh[NE * NH * ND];
__device__ float  g_dcomb[NE * NH];

// ---------------- PTX helpers ----------------------------------------------
__device__ __forceinline__ u32 smem_u32(const void* p) {
    u32 a;
    asm("{ .reg .u64 t; cvta.to.shared.u64 t, %1; cvt.u32.u64 %0, t; }" : "=r"(a) : "l"(p));
    return a;
}
__device__ __forceinline__ void cp16(u32 dst, const void* src) {
    asm volatile("cp.async.cg.shared.global [%0], [%1], 16;" :: "r"(dst), "l"(src) : "memory");
}
__device__ __forceinline__ void cp_commit() { asm volatile("cp.async.commit_group;" ::: "memory"); }
__device__ __forceinline__ void cp_wait2()  { asm volatile("cp.async.wait_group 2;" ::: "memory"); }

__device__ __forceinline__ void ldsm4(u32& r0, u32& r1, u32& r2, u32& r3, u32 addr) {
    asm volatile("ldmatrix.sync.aligned.m8n8.x4.shared.b16 {%0,%1,%2,%3}, [%4];"
                 : "=r"(r0), "=r"(r1), "=r"(r2), "=r"(r3) : "r"(addr));
}
__device__ __forceinline__ void mma16816(float* c, const u32* a, const u32* b) {
    asm volatile("mma.sync.aligned.m16n8k16.row.col.f32.f16.f16.f32 "
                 "{%0,%1,%2,%3}, {%4,%5,%6,%7}, {%8,%9}, {%0,%1,%2,%3};"
                 : "+f"(c[0]), "+f"(c[1]), "+f"(c[2]), "+f"(c[3])
                 : "r"(a[0]), "r"(a[1]), "r"(a[2]), "r"(a[3]), "r"(b[0]), "r"(b[1]));
}

__device__ __forceinline__ u32 swz128(u32 off) { return off ^ ((off >> 3) & 0x70); }

// ---------------- fused prep kernel ------------------------------------------
// blocks [0, 4096): W rows -> fp16 + d = bias - c_e.W_row  (1 warp per row)
// blocks [4096, 6144): x -> fp16
__global__ void prep_kernel(const float* __restrict__ x,
                            const float* __restrict__ W,
                            const float* __restrict__ centers,
                            const float* __restrict__ bias) {
    int b = blockIdx.x;
    if (b < 4096) {
        int gw   = b * 8 + (threadIdx.x >> 5);
        int lane = threadIdx.x & 31;
        int e = gw >> 11;
        const float4* wr = (const float4*)(W + (size_t)gw * ND);
        const float4* cr = (const float4*)(centers + (size_t)e * ND);
        __half2* ph = (__half2*)(g_wh + (size_t)gw * ND);
        float s = 0.f;
#pragma unroll
        for (int i = 0; i < ND / 128; i++) {
            int idx = lane + 32 * i;
            float4 w4 = wr[idx];
            float4 c4 = cr[idx];
            s += w4.x * c4.x + w4.y * c4.y + w4.z * c4.z + w4.w * c4.w;
            ph[2 * idx]     = __half2(__float2half_rn(w4.x), __float2half_rn(w4.y));
            ph[2 * idx + 1] = __half2(__float2half_rn(w4.z), __float2half_rn(w4.w));
        }
#pragma unroll
        for (int o = 16; o; o >>= 1) s += __shfl_xor_sync(0xffffffffu, s, o);
        if (lane == 0) g_dcomb[gw] = bias[gw] - s;
    } else {
        int i = (b - 4096) * 256 + threadIdx.x;
        float4 v = ((const float4*)x)[i];
        __half2* ph = (__half2*)g_xh;
        ph[2 * i]     = __half2(__float2half_rn(v.x), __float2half_rn(v.y));
        ph[2 * i + 1] = __half2(__float2half_rn(v.z), __float2half_rn(v.w));
    }
}

// ---------------- main GEMM kernel -------------------------------------------
// grid (NH/64, NB/128) = (32, 32) = 1024 CTAs; 128 threads (4 warps), occ 2.
// Warp tile 64x32: wm = (wid>>1)*64, wn = (wid&1)*32.
// 128 chunks = 16 experts x 8 k-chunks of 64; per-chunk barrier; register
// fragment double-buffering; 4-stage cp.async ring, distance 3.

__device__ __forceinline__ void load_chunk(int gc, u32 dst, int mb, int hb, int tid) {
    int e = gc >> 3, kc = (gc & 7) * KC;
    // X tile 128x64: thread t loads row t (8 x cp16 = 128 B)
    const __half* px = g_xh + (size_t)(mb + tid) * ND + kc;
#pragma unroll
    for (int i = 0; i < 8; i++)
        cp16(dst + swz128((u32)(tid * 128 + i * 16)), px + i * 8);
    // W tile 64x64: thread t loads row (t&63), half (t>>6) (4 x cp16 = 64 B)
    int wrow = tid & 63, wh = tid >> 6;
    const __half* pw = g_wh + (size_t)(e * NH + hb + wrow) * ND + kc + wh * 32;
#pragma unroll
    for (int i = 0; i < 4; i++)
        cp16(dst + XTILE + swz128((u32)(wrow * 128 + wh * 64 + i * 16)), pw + i * 8);
}

__device__ __forceinline__ void load_frags(int ks, u32 Ah, u32 Bh, int wm, int wn,
                                           int lane, u32 ah[4][4], u32 bh[4][2]) {
    u32 arel = swz128((u32)((lane & 15) * 128 + ks * 32 + (lane >> 4) * 16));
#pragma unroll
    for (int mt = 0; mt < 4; mt++) {
        u32 ao = (u32)((wm + mt * 16) * 128) + arel;
        ldsm4(ah[mt][0], ah[mt][1], ah[mt][2], ah[mt][3], Ah + ao);
    }
    u32 brel = swz128((u32)((lane & 7) * 128 + ks * 32 + ((lane >> 3) & 1) * 16));
#pragma unroll
    for (int pr = 0; pr < 2; pr++) {
        u32 bo = (u32)((wn + pr * 16 + ((lane >> 4) & 1) * 8) * 128) + brel;
        ldsm4(bh[pr * 2][0], bh[pr * 2][1], bh[pr * 2 + 1][0], bh[pr * 2 + 1][1], Bh + bo);
    }
}

__global__ void __launch_bounds__(128, 2)
gemm_kernel(float* __restrict__ out) {
    extern __shared__ char smem[];
    float* dsm = (float*)smem;                     // [16][64] combined bias
    u32 sb = smem_u32(smem) + OFF_STAGES;
    const int tid = threadIdx.x, wid = tid >> 5, lane = tid & 31;
    const int hb = blockIdx.x * 64, mb = blockIdx.y * 128;
    const int wm = (wid >> 1) * 64, wn = (wid & 1) * 32;

    // stage the per-expert combined bias slice for this CTA
#pragma unroll
    for (int i = tid; i < NE * 64; i += 128)
        dsm[i] = g_dcomb[(size_t)(i >> 6) * NH + hb + (i & 63)];

    load_chunk(0, sb + 0 * STAGE, mb, hb, tid); cp_commit();
    load_chunk(1, sb + 1 * STAGE, mb, hb, tid); cp_commit();
    load_chunk(2, sb + 2 * STAGE, mb, hb, tid); cp_commit();

    float acc[4][4][4], oacc[4][4][4];
#pragma unroll
    for (int a = 0; a < 4; a++)
#pragma unroll
        for (int b = 0; b < 4; b++)
#pragma unroll
            for (int c = 0; c < 4; c++) { acc[a][b][c] = 0.f; oacc[a][b][c] = 0.f; }

    u32 ah[2][4][4], bh[2][4][2];

    for (int gc = 0; gc < 128; gc++) {
        cp_wait2();
        __syncthreads();

        u32 st = sb + (u32)(gc & 3) * STAGE;
        u32 Ah = st, Bh = st + XTILE;

        // fragment double buffer: ks0 loads right after the barrier
        load_frags(0, Ah, Bh, wm, wn, lane, ah[0], bh[0]);

        // prefetch chunk gc+3 into stage (gc+3)&3 = (gc-1)&3 (consumed last iter;
        // the barrier above proves all warps are past it)
        if (gc + 3 < 128) load_chunk(gc + 3, sb + (u32)((gc + 3) & 3) * STAGE, mb, hb, tid);
        cp_commit();

#pragma unroll
        for (int ks = 0; ks < 4; ks++) {
            int cur = ks & 1;
            if (ks < 3)
                load_frags(ks + 1, Ah, Bh, wm, wn, lane, ah[cur ^ 1], bh[cur ^ 1]);
#pragma unroll
            for (int mt = 0; mt < 4; mt++)
#pragma unroll
                for (int nt = 0; nt < 4; nt++)
                    mma16816(acc[mt][nt], ah[cur][mt], bh[cur][nt]);
        }

        if ((gc & 7) == 7) {    // finished expert e: relu + accumulate, reset
            int e = gc >> 3;
            const float2* dp = (const float2*)(dsm + e * 64 + wn);
#pragma unroll
            for (int nt = 0; nt < 4; nt++) {
                float2 d2 = dp[nt * 4 + (lane & 3)];
#pragma unroll
                for (int mt = 0; mt < 4; mt++) {
                    oacc[mt][nt][0] += fmaxf(acc[mt][nt][0] + d2.x, 0.f);
                    oacc[mt][nt][1] += fmaxf(acc[mt][nt][1] + d2.y, 0.f);
                    oacc[mt][nt][2] += fmaxf(acc[mt][nt][2] + d2.x, 0.f);
                    oacc[mt][nt][3] += fmaxf(acc[mt][nt][3] + d2.y, 0.f);
                    acc[mt][nt][0] = 0.f; acc[mt][nt][1] = 0.f;
                    acc[mt][nt][2] = 0.f; acc[mt][nt][3] = 0.f;
                }
            }
        }
    }

    // store: C fragment mapping — (row t/4 [+8], col 2*(t%4) [+1])
#pragma unroll
    for (int mt = 0; mt < 4; mt++)
#pragma unroll
        for (int nt = 0; nt < 4; nt++) {
            int r0 = mb + wm + mt * 16 + (lane >> 2);
            int cc = hb + wn + nt * 8 + 2 * (lane & 3);
            *(float2*)(out + (size_t)r0 * NH + cc) =
                make_float2(oacc[mt][nt][0], oacc[mt][nt][1]);
            *(float2*)(out + (size_t)(r0 + 8) * NH + cc) =
                make_float2(oacc[mt][nt][2], oacc[mt][nt][3]);
        }
}

// ---------------- launch -----------------------------------------------------
extern "C" void kernel_launch(void* const* d_in, const int* in_sizes, int n_in,
                              void* d_out, int out_size) {
    const float* x       = (const float*)d_in[0];  // [B, D]
    const float* centers = (const float*)d_in[1];  // [E, D]
    const float* W       = (const float*)d_in[2];  // [E, H, D]
    const float* bias    = (const float*)d_in[3];  // [E, H]
    float* out = (float*)d_out;                    // [B, H]

    cudaFuncSetAttribute(gemm_kernel, cudaFuncAttributeMaxDynamicSharedMemorySize, SMEM_TOTAL);

    prep_kernel<<<4096 + 2048, 256>>>(x, W, centers, bias);

    dim3 grid(NH / 64, NB / 128);    // (32, 32) = 1024 CTAs
    gemm_kernel<<<grid, 128, SMEM_TOTAL>>>(out);
}

// round 11
// speedup vs baseline: 1.8187x; 1.8187x over previous
#include <cuda_runtime.h>
#include <cuda_fp16.h>
#include <cstdint>

typedef unsigned long long u64;
typedef uint32_t u32;

#define NB 4096
#define NE 16
#define ND 512
#define NH 2048

#define KC 64                          // k-chunk: 64 fp16 = 128B rows
#define TILE 16384                     // 128 x 64 fp16 tile bytes
#define NWSTAGE 6
#define OFF_DBUF 0                     // 512B: current-expert bias slice
#define OFF_X    1024                  // 8 x-tiles, 131072 B (static all-K x)
#define OFF_W    132096                // 6 W stages, 98304 B
#define SMEM_TOTAL (OFF_W + NWSTAGE * TILE)        // 230400 B

// ---------------- scratch (device globals; no allocations allowed) ----------
__device__ __half g_xh[NB * ND];
__device__ __half g_wh[NE * NH * ND];
__device__ float  g_dcomb[NE * NH];

// ---------------- PTX helpers ----------------------------------------------
__device__ __forceinline__ u32 smem_u32(const void* p) {
    u32 a;
    asm("{ .reg .u64 t; cvta.to.shared.u64 t, %1; cvt.u32.u64 %0, t; }" : "=r"(a) : "l"(p));
    return a;
}
__device__ __forceinline__ void cp16(u32 dst, const void* src) {
    asm volatile("cp.async.cg.shared.global [%0], [%1], 16;" :: "r"(dst), "l"(src) : "memory");
}
__device__ __forceinline__ void cp_commit() { asm volatile("cp.async.commit_group;" ::: "memory"); }
__device__ __forceinline__ void cp_wait1()  { asm volatile("cp.async.wait_group 1;" ::: "memory"); }

__device__ __forceinline__ void ldsm4(u32& r0, u32& r1, u32& r2, u32& r3, u32 addr) {
    asm volatile("ldmatrix.sync.aligned.m8n8.x4.shared.b16 {%0,%1,%2,%3}, [%4];"
                 : "=r"(r0), "=r"(r1), "=r"(r2), "=r"(r3) : "r"(addr));
}
__device__ __forceinline__ void mma16816(float* c, const u32* a, const u32* b) {
    asm volatile("mma.sync.aligned.m16n8k16.row.col.f32.f16.f16.f32 "
                 "{%0,%1,%2,%3}, {%4,%5,%6,%7}, {%8,%9}, {%0,%1,%2,%3};"
                 : "+f"(c[0]), "+f"(c[1]), "+f"(c[2]), "+f"(c[3])
                 : "r"(a[0]), "r"(a[1]), "r"(a[2]), "r"(a[3]), "r"(b[0]), "r"(b[1]));
}

__device__ __forceinline__ u32 swz128(u32 off) { return off ^ ((off >> 3) & 0x70); }

// ---------------- fused prep kernel ------------------------------------------
// blocks [0, 4096): W rows -> fp16 + d = bias - c_e.W_row  (1 warp per row)
// blocks [4096, 6144): x -> fp16
__global__ void prep_kernel(const float* __restrict__ x,
                            const float* __restrict__ W,
                            const float* __restrict__ centers,
                            const float* __restrict__ bias) {
    int b = blockIdx.x;
    if (b < 4096) {
        int gw   = b * 8 + (threadIdx.x >> 5);
        int lane = threadIdx.x & 31;
        int e = gw >> 11;
        const float4* wr = (const float4*)(W + (size_t)gw * ND);
        const float4* cr = (const float4*)(centers + (size_t)e * ND);
        __half2* ph = (__half2*)(g_wh + (size_t)gw * ND);
        float s = 0.f;
#pragma unroll
        for (int i = 0; i < ND / 128; i++) {
            int idx = lane + 32 * i;
            float4 w4 = wr[idx];
            float4 c4 = cr[idx];
            s += w4.x * c4.x + w4.y * c4.y + w4.z * c4.z + w4.w * c4.w;
            ph[2 * idx]     = __half2(__float2half_rn(w4.x), __float2half_rn(w4.y));
            ph[2 * idx + 1] = __half2(__float2half_rn(w4.z), __float2half_rn(w4.w));
        }
#pragma unroll
        for (int o = 16; o; o >>= 1) s += __shfl_xor_sync(0xffffffffu, s, o);
        if (lane == 0) g_dcomb[gw] = bias[gw] - s;
    } else {
        int i = (b - 4096) * 256 + threadIdx.x;
        float4 v = ((const float4*)x)[i];
        __half2* ph = (__half2*)g_xh;
        ph[2 * i]     = __half2(__float2half_rn(v.x), __float2half_rn(v.y));
        ph[2 * i + 1] = __half2(__float2half_rn(v.z), __float2half_rn(v.w));
    }
}

// ---------------- main GEMM kernel -------------------------------------------
// grid (NH/128, NB/128) = (16, 32); 256 threads, 8 warps (2m x 4n of 64x32).
// X (128x512) resident in smem (8 chunk-tiles, loaded once). Per chunk only the
// W tile (128x64) streams through a 6-stage ring; 2 chunks per barrier;
// fragment ping-pong pipelined across the intra-pair boundary.

__device__ __forceinline__ void load_wchunk(int gc, u32 sbW, int hb, int tid) {
    int e = gc >> 3, kc = (gc & 7) * KC;
    u32 dst = sbW + (u32)(gc % NWSTAGE) * TILE;
    int r = tid >> 1, h = tid & 1;
    const __half* pw = g_wh + (size_t)(e * NH + hb + r) * ND + kc + h * 32;
#pragma unroll
    for (int i = 0; i < 4; i++)
        cp16(dst + swz128((u32)(r * 128 + h * 64 + i * 16)), pw + i * 8);
}

__device__ __forceinline__ void load_frags(int ks, u32 Ah, u32 Bh, int wm, int wn,
                                           int lane, u32 ah[4][4], u32 bh[4][2]) {
    u32 arel = swz128((u32)((lane & 15) * 128 + ks * 32 + (lane >> 4) * 16));
#pragma unroll
    for (int mt = 0; mt < 4; mt++) {
        u32 ao = (u32)((wm + mt * 16) * 128) + arel;
        ldsm4(ah[mt][0], ah[mt][1], ah[mt][2], ah[mt][3], Ah + ao);
    }
    u32 brel = swz128((u32)((lane & 7) * 128 + ks * 32 + ((lane >> 3) & 1) * 16));
#pragma unroll
    for (int pr = 0; pr < 2; pr++) {
        u32 bo = (u32)((wn + pr * 16 + ((lane >> 4) & 1) * 8) * 128) + brel;
        ldsm4(bh[pr * 2][0], bh[pr * 2][1], bh[pr * 2 + 1][0], bh[pr * 2 + 1][1], Bh + bo);
    }
}

__global__ void __launch_bounds__(256, 1)
gemm_kernel(float* __restrict__ out) {
    extern __shared__ char smem[];
    float* dbuf = (float*)smem;                    // [128] current-expert bias
    u32 sb  = smem_u32(smem);
    u32 sbX = sb + OFF_X, sbW = sb + OFF_W;
    const int tid = threadIdx.x, wid = tid >> 5, lane = tid & 31;
    const int hb = blockIdx.x * 128, mb = blockIdx.y * 128;
    const int wm = (wid >> 2) * 64, wn = (wid & 3) * 32;

    // prologue: X fully resident (one cp.async group), then W groups G0, G1
    {
        int r = tid >> 1, h = tid & 1;
        const __half* px = g_xh + (size_t)(mb + r) * ND + h * 32;
#pragma unroll
        for (int t = 0; t < 8; t++)
#pragma unroll
            for (int i = 0; i < 4; i++)
                cp16(sbX + (u32)t * TILE + swz128((u32)(r * 128 + h * 64 + i * 16)),
                     px + t * 64 + i * 8);
    }
    cp_commit();
    load_wchunk(0, sbW, hb, tid);
    load_wchunk(1, sbW, hb, tid); cp_commit();
    load_wchunk(2, sbW, hb, tid);
    load_wchunk(3, sbW, hb, tid); cp_commit();

    float acc[4][4][4], oacc[4][4][4];
#pragma unroll
    for (int a = 0; a < 4; a++)
#pragma unroll
        for (int b = 0; b < 4; b++)
#pragma unroll
            for (int c = 0; c < 4; c++) { acc[a][b][c] = 0.f; oacc[a][b][c] = 0.f; }

    u32 ah[2][4][4], bh[2][4][2];

    for (int j = 0; j < 64; j++) {     // iteration = chunk pair (2j, 2j+1)
        int c0 = 2 * j;
        cp_wait1();                    // X + groups up to G_j complete
        __syncthreads();

        // stage the bias slice for the expert finishing at pair j|3
        if ((j & 3) == 0 && tid < 128)
            dbuf[tid] = g_dcomb[(size_t)(j >> 2) * NH + hb + tid];

        u32 A0 = sbX + (u32)(c0 & 7) * TILE;
        u32 A1 = sbX + (u32)((c0 + 1) & 7) * TILE;
        u32 B0 = sbW + (u32)(c0 % NWSTAGE) * TILE;
        u32 B1 = sbW + (u32)((c0 + 1) % NWSTAGE) * TILE;

        load_frags(0, A0, B0, wm, wn, lane, ah[0], bh[0]);

        if (c0 + 4 < 128) {            // prefetch W group j+2
            load_wchunk(c0 + 4, sbW, hb, tid);
            load_wchunk(c0 + 5, sbW, hb, tid);
        }
        cp_commit();

        // chunk c0: at ks3 preload chunk c1's ks0 (same barrier scope)
#pragma unroll
        for (int ks = 0; ks < 4; ks++) {
            int cur = ks & 1;
            if (ks < 3) load_frags(ks + 1, A0, B0, wm, wn, lane, ah[cur ^ 1], bh[cur ^ 1]);
            else        load_frags(0,      A1, B1, wm, wn, lane, ah[cur ^ 1], bh[cur ^ 1]);
#pragma unroll
            for (int mt = 0; mt < 4; mt++)
#pragma unroll
                for (int nt = 0; nt < 4; nt++)
                    mma16816(acc[mt][nt], ah[cur][mt], bh[cur][nt]);
        }

        // chunk c1
#pragma unroll
        for (int ks = 0; ks < 4; ks++) {
            int cur = ks & 1;
            if (ks < 3) load_frags(ks + 1, A1, B1, wm, wn, lane, ah[cur ^ 1], bh[cur ^ 1]);
#pragma unroll
            for (int mt = 0; mt < 4; mt++)
#pragma unroll
                for (int nt = 0; nt < 4; nt++)
                    mma16816(acc[mt][nt], ah[cur][mt], bh[cur][nt]);
        }

        if ((j & 3) == 3) {            // finished expert: relu + accumulate
            const float2* dp = (const float2*)(dbuf + wn);
#pragma unroll
            for (int nt = 0; nt < 4; nt++) {
                float2 d2 = dp[nt * 4 + (lane & 3)];
#pragma unroll
                for (int mt = 0; mt < 4; mt++) {
                    oacc[mt][nt][0] += fmaxf(acc[mt][nt][0] + d2.x, 0.f);
                    oacc[mt][nt][1] += fmaxf(acc[mt][nt][1] + d2.y, 0.f);
                    oacc[mt][nt][2] += fmaxf(acc[mt][nt][2] + d2.x, 0.f);
                    oacc[mt][nt][3] += fmaxf(acc[mt][nt][3] + d2.y, 0.f);
                    acc[mt][nt][0] = 0.f; acc[mt][nt][1] = 0.f;
                    acc[mt][nt][2] = 0.f; acc[mt][nt][3] = 0.f;
                }
            }
        }
    }

    // store: C fragment mapping — (row t/4 [+8], col 2*(t%4) [+1])
#pragma unroll
    for (int mt = 0; mt < 4; mt++)
#pragma unroll
        for (int nt = 0; nt < 4; nt++) {
            int r0 = mb + wm + mt * 16 + (lane >> 2);
            int cc = hb + wn + nt * 8 + 2 * (lane & 3);
            *(float2*)(out + (size_t)r0 * NH + cc) =
                make_float2(oacc[mt][nt][0], oacc[mt][nt][1]);
            *(float2*)(out + (size_t)(r0 + 8) * NH + cc) =
                make_float2(oacc[mt][nt][2], oacc[mt][nt][3]);
        }
}

// ---------------- launch -----------------------------------------------------
extern "C" void kernel_launch(void* const* d_in, const int* in_sizes, int n_in,
                              void* d_out, int out_size) {
    const float* x       = (const float*)d_in[0];  // [B, D]
    const float* centers = (const float*)d_in[1];  // [E, D]
    const float* W       = (const float*)d_in[2];  // [E, H, D]
    const float* bias    = (const float*)d_in[3];  // [E, H]
    float* out = (float*)d_out;                    // [B, H]

    cudaFuncSetAttribute(gemm_kernel, cudaFuncAttributeMaxDynamicSharedMemorySize, SMEM_TOTAL);

    prep_kernel<<<4096 + 2048, 256>>>(x, W, centers, bias);

    dim3 grid(NH / 128, NB / 128);   // (16, 32)
    gemm_kernel<<<grid, 256, SMEM_TOTAL>>>(out);
}

// round 12
// speedup vs baseline: 2.0292x; 1.1158x over previous
#include <cuda_runtime.h>
#include <cuda_fp16.h>
#include <cstdint>

typedef unsigned long long u64;
typedef uint32_t u32;

#define NB 4096
#define NE 16
#define ND 512
#define NH 2048

#define KC 64                          // k-chunk: 64 fp16 = 128B rows
#define TILE 16384                     // 128 x 64 fp16 tile bytes
#define STAGE (2 * TILE)               // x tile + w tile per chunk
#define NSTAGE 6
#define OFF_STAGES 8192                // after d-table (16*128 floats)
#define SMEM_TOTAL (OFF_STAGES + NSTAGE * STAGE)   // 204800 B

// ---------------- scratch (device globals; no allocations allowed) ----------
__device__ __half g_xh[NB * ND];
__device__ __half g_wh[NE * NH * ND];
__device__ float  g_dcomb[NE * NH];

// ---------------- PTX helpers ----------------------------------------------
__device__ __forceinline__ u32 smem_u32(const void* p) {
    u32 a;
    asm("{ .reg .u64 t; cvta.to.shared.u64 t, %1; cvt.u32.u64 %0, t; }" : "=r"(a) : "l"(p));
    return a;
}
__device__ __forceinline__ void cp16(u32 dst, const void* src) {
    asm volatile("cp.async.cg.shared.global [%0], [%1], 16;" :: "r"(dst), "l"(src) : "memory");
}
__device__ __forceinline__ void cp_commit() { asm volatile("cp.async.commit_group;" ::: "memory"); }
__device__ __forceinline__ void cp_wait0()  { asm volatile("cp.async.wait_group 0;" ::: "memory"); }
__device__ __forceinline__ void cp_wait1()  { asm volatile("cp.async.wait_group 1;" ::: "memory"); }

__device__ __forceinline__ void ldsm4(u32& r0, u32& r1, u32& r2, u32& r3, u32 addr) {
    asm volatile("ldmatrix.sync.aligned.m8n8.x4.shared.b16 {%0,%1,%2,%3}, [%4];"
                 : "=r"(r0), "=r"(r1), "=r"(r2), "=r"(r3) : "r"(addr));
}
__device__ __forceinline__ void mma16816(float* c, const u32* a, const u32* b) {
    asm volatile("mma.sync.aligned.m16n8k16.row.col.f32.f16.f16.f32 "
                 "{%0,%1,%2,%3}, {%4,%5,%6,%7}, {%8,%9}, {%0,%1,%2,%3};"
                 : "+f"(c[0]), "+f"(c[1]), "+f"(c[2]), "+f"(c[3])
                 : "r"(a[0]), "r"(a[1]), "r"(a[2]), "r"(a[3]), "r"(b[0]), "r"(b[1]));
}

__device__ __forceinline__ u32 swz128(u32 off) { return off ^ ((off >> 3) & 0x70); }

// ---------------- fused prep kernel ------------------------------------------
// blocks [0, 4096): W rows -> fp16 + d = bias - c_e.W_row  (1 warp per row)
// blocks [4096, 6144): x -> fp16
__global__ void prep_kernel(const float* __restrict__ x,
                            const float* __restrict__ W,
                            const float* __restrict__ centers,
                            const float* __restrict__ bias) {
    int b = blockIdx.x;
    if (b < 4096) {
        int gw   = b * 8 + (threadIdx.x >> 5);
        int lane = threadIdx.x & 31;
        int e = gw >> 11;
        const float4* wr = (const float4*)(W + (size_t)gw * ND);
        const float4* cr = (const float4*)(centers + (size_t)e * ND);
        __half2* ph = (__half2*)(g_wh + (size_t)gw * ND);
        float s = 0.f;
#pragma unroll
        for (int i = 0; i < ND / 128; i++) {
            int idx = lane + 32 * i;
            float4 w4 = wr[idx];
            float4 c4 = cr[idx];
            s += w4.x * c4.x + w4.y * c4.y + w4.z * c4.z + w4.w * c4.w;
            ph[2 * idx]     = __half2(__float2half_rn(w4.x), __float2half_rn(w4.y));
            ph[2 * idx + 1] = __half2(__float2half_rn(w4.z), __float2half_rn(w4.w));
        }
#pragma unroll
        for (int o = 16; o; o >>= 1) s += __shfl_xor_sync(0xffffffffu, s, o);
        if (lane == 0) g_dcomb[gw] = bias[gw] - s;
    } else {
        int i = (b - 4096) * 256 + threadIdx.x;
        float4 v = ((const float4*)x)[i];
        __half2* ph = (__half2*)g_xh;
        ph[2 * i]     = __half2(__float2half_rn(v.x), __float2half_rn(v.y));
        ph[2 * i + 1] = __half2(__float2half_rn(v.z), __float2half_rn(v.w));
    }
}

// ---------------- main GEMM kernel -------------------------------------------
// grid (NH/128, NB/128) = (16, 32); 256 threads, 8 warps (2m x 4n of 64x32).
// 128 chunks = 16 experts x 8 k-chunks of 64; 2 chunks per barrier.
// Fragment ping-pong pipelined across chunk AND pair boundaries: the next
// pair's ks0 fragments are preloaded pre-barrier (legal under wait_group 0 +
// barrier: all warps' cp.asyncs for that stage completed a pair earlier).

__device__ __forceinline__ void load_chunk(int gc, u32 dst, int mb, int hb, int tid) {
    int e = gc >> 3, kc = (gc & 7) * KC;
    int row = tid >> 3, c = tid & 7;
    u32 so = swz128((u32)(row * 128 + c * 16));
    const __half* pxh = g_xh + (size_t)(mb + row) * ND + kc + c * 8;
    const __half* pwh = g_wh + (size_t)(e * NH + hb + row) * ND + kc + c * 8;
#pragma unroll
    for (int i = 0; i < 4; i++) {
        u32 d = dst + so + (u32)i * 4096;          // +32 rows per step
        size_t eo = (size_t)(32 * i) * ND;
        cp16(d + 0 * TILE, pxh + eo);
        cp16(d + 1 * TILE, pwh + eo);
    }
}

__device__ __forceinline__ void load_frags(int ks, u32 Ah, u32 Bh, int wm, int wn,
                                           int lane, u32 ah[4][4], u32 bh[4][2]) {
    u32 arel = swz128((u32)((lane & 15) * 128 + ks * 32 + (lane >> 4) * 16));
#pragma unroll
    for (int mt = 0; mt < 4; mt++) {
        u32 ao = (u32)((wm + mt * 16) * 128) + arel;
        ldsm4(ah[mt][0], ah[mt][1], ah[mt][2], ah[mt][3], Ah + ao);
    }
    u32 brel = swz128((u32)((lane & 7) * 128 + ks * 32 + ((lane >> 3) & 1) * 16));
#pragma unroll
    for (int pr = 0; pr < 2; pr++) {
        u32 bo = (u32)((wn + pr * 16 + ((lane >> 4) & 1) * 8) * 128) + brel;
        ldsm4(bh[pr * 2][0], bh[pr * 2][1], bh[pr * 2 + 1][0], bh[pr * 2 + 1][1], Bh + bo);
    }
}

__global__ void __launch_bounds__(256, 1)
gemm_kernel(float* __restrict__ out) {
    extern __shared__ char smem[];
    float* dsm = (float*)smem;                     // [16][128] combined bias
    u32 sb = smem_u32(smem) + OFF_STAGES;
    const int tid = threadIdx.x, wid = tid >> 5, lane = tid & 31;
    const int hb = blockIdx.x * 128, mb = blockIdx.y * 128;
    const int wm = (wid >> 2) * 64, wn = (wid & 3) * 32;

    // stage the per-expert combined bias slice for this CTA
#pragma unroll
    for (int i = tid; i < NE * 128; i += 256)
        dsm[i] = g_dcomb[(size_t)(i >> 7) * NH + hb + (i & 127)];

    // prologue: group G0 = chunks 0,1; G1 = chunks 2,3
    load_chunk(0, sb + 0 * STAGE, mb, hb, tid);
    load_chunk(1, sb + 1 * STAGE, mb, hb, tid); cp_commit();
    load_chunk(2, sb + 2 * STAGE, mb, hb, tid);
    load_chunk(3, sb + 3 * STAGE, mb, hb, tid); cp_commit();

    float acc[4][4][4], oacc[4][4][4];
#pragma unroll
    for (int a = 0; a < 4; a++)
#pragma unroll
        for (int b = 0; b < 4; b++)
#pragma unroll
            for (int c = 0; c < 4; c++) { acc[a][b][c] = 0.f; oacc[a][b][c] = 0.f; }

    u32 ah[2][4][4], bh[2][4][2];

    // prime buf0 with chunk 0 ks0 (G0 complete after wait1 + barrier)
    cp_wait1();
    __syncthreads();
    load_frags(0, sb, sb + TILE, wm, wn, lane, ah[0], bh[0]);

    for (int j = 0; j < 64; j++) {     // iteration = chunk pair (2j, 2j+1)
        int c0 = 2 * j;
        // wait0: ALL own groups (incl. G(j+1)) done; barrier makes it collective,
        // which legalizes this pair's end-of-pair preload of chunk 2j+2.
        cp_wait0();
        __syncthreads();

        u32 s0 = sb + (u32)(c0 % NSTAGE) * STAGE;
        u32 s1 = sb + (u32)((c0 + 1) % NSTAGE) * STAGE;
        u32 A0 = s0, B0 = s0 + TILE, A1 = s1, B1 = s1 + TILE;

        if (c0 + 4 < 128) {            // prefetch group j+2 = chunks 2j+4, 2j+5
            load_chunk(c0 + 4, sb + (u32)((c0 + 4) % NSTAGE) * STAGE, mb, hb, tid);
            load_chunk(c0 + 5, sb + (u32)((c0 + 5) % NSTAGE) * STAGE, mb, hb, tid);
        }
        cp_commit();

        // chunk c0: ks0 frags already resident in buf0; at ks3 preload c1's ks0
#pragma unroll
        for (int ks = 0; ks < 4; ks++) {
            int cur = ks & 1;
            if (ks < 3) load_frags(ks + 1, A0, B0, wm, wn, lane, ah[cur ^ 1], bh[cur ^ 1]);
            else        load_frags(0,      A1, B1, wm, wn, lane, ah[cur ^ 1], bh[cur ^ 1]);
#pragma unroll
            for (int mt = 0; mt < 4; mt++)
#pragma unroll
                for (int nt = 0; nt < 4; nt++)
                    mma16816(acc[mt][nt], ah[cur][mt], bh[cur][nt]);
        }

        // chunk c1; at ks3 preload NEXT PAIR's ks0 (chunk 2j+2) pre-barrier
#pragma unroll
        for (int ks = 0; ks < 4; ks++) {
            int cur = ks & 1;
            if (ks < 3) {
                load_frags(ks + 1, A1, B1, wm, wn, lane, ah[cur ^ 1], bh[cur ^ 1]);
            } else if (c0 + 2 < 128) {
                u32 s2 = sb + (u32)((c0 + 2) % NSTAGE) * STAGE;
                load_frags(0, s2, s2 + TILE, wm, wn, lane, ah[cur ^ 1], bh[cur ^ 1]);
            }
#pragma unroll
            for (int mt = 0; mt < 4; mt++)
#pragma unroll
                for (int nt = 0; nt < 4; nt++)
                    mma16816(acc[mt][nt], ah[cur][mt], bh[cur][nt]);
        }

        if ((j & 3) == 3) {            // finished expert e = j>>2: relu + accumulate
            int e = j >> 2;
            const float2* dp = (const float2*)(dsm + e * 128 + wn);
#pragma unroll
            for (int nt = 0; nt < 4; nt++) {
                float2 d2 = dp[nt * 4 + (lane & 3)];
#pragma unroll
                for (int mt = 0; mt < 4; mt++) {
                    oacc[mt][nt][0] += fmaxf(acc[mt][nt][0] + d2.x, 0.f);
                    oacc[mt][nt][1] += fmaxf(acc[mt][nt][1] + d2.y, 0.f);
                    oacc[mt][nt][2] += fmaxf(acc[mt][nt][2] + d2.x, 0.f);
                    oacc[mt][nt][3] += fmaxf(acc[mt][nt][3] + d2.y, 0.f);
                    acc[mt][nt][0] = 0.f; acc[mt][nt][1] = 0.f;
                    acc[mt][nt][2] = 0.f; acc[mt][nt][3] = 0.f;
                }
            }
        }
    }

    // store: C fragment mapping — (row t/4 [+8], col 2*(t%4) [+1])
#pragma unroll
    for (int mt = 0; mt < 4; mt++)
#pragma unroll
        for (int nt = 0; nt < 4; nt++) {
            int r0 = mb + wm + mt * 16 + (lane >> 2);
            int cc = hb + wn + nt * 8 + 2 * (lane & 3);
            *(float2*)(out + (size_t)r0 * NH + cc) =
                make_float2(oacc[mt][nt][0], oacc[mt][nt][1]);
            *(float2*)(out + (size_t)(r0 + 8) * NH + cc) =
                make_float2(oacc[mt][nt][2], oacc[mt][nt][3]);
        }
}

// ---------------- launch -----------------------------------------------------
extern "C" void kernel_launch(void* const* d_in, const int* in_sizes, int n_in,
                              void* d_out, int out_size) {
    const float* x       = (const float*)d_in[0];  // [B, D]
    const float* centers = (const float*)d_in[1];  // [E, D]
    const float* W       = (const float*)d_in[2];  // [E, H, D]
    const float* bias    = (const float*)d_in[3];  // [E, H]
    float* out = (float*)d_out;                    // [B, H]

    cudaFuncSetAttribute(gemm_kernel, cudaFuncAttributeMaxDynamicSharedMemorySize, SMEM_TOTAL);

    prep_kernel<<<4096 + 2048, 256>>>(x, W, centers, bias);

    dim3 grid(NH / 128, NB / 128);   // (16, 32)
    gemm_kernel<<<grid, 256, SMEM_TOTAL>>>(out);
}

// round 13
// speedup vs baseline: 2.2565x; 1.1120x over previous
#include <cuda_runtime.h>
#include <cuda_fp16.h>
#include <cstdint>

typedef unsigned long long u64;
typedef uint32_t u32;

#define NB 4096
#define NE 16
#define ND 512
#define NH 2048

#define KC 64                          // k-chunk: 64 fp16 = 128B rows
#define TILE 16384                     // 128 x 64 fp16 tile bytes
#define STAGE (2 * TILE)               // x tile + w tile per chunk
#define NSTAGE 6
#define OFF_STAGES 4096                // after d-table (8*128 floats)
#define SMEM_TOTAL (OFF_STAGES + NSTAGE * STAGE)   // 200704 B

// ---------------- scratch (device globals; no allocations allowed) ----------
__device__ __half g_xh[NB * ND];
__device__ __half g_wh[NE * NH * ND];
__device__ float  g_dcomb[NE * NH];

// ---------------- PTX helpers ----------------------------------------------
__device__ __forceinline__ u32 smem_u32(const void* p) {
    u32 a;
    asm("{ .reg .u64 t; cvta.to.shared.u64 t, %1; cvt.u32.u64 %0, t; }" : "=r"(a) : "l"(p));
    return a;
}
__device__ __forceinline__ void cp16(u32 dst, const void* src) {
    asm volatile("cp.async.cg.shared.global [%0], [%1], 16;" :: "r"(dst), "l"(src) : "memory");
}
__device__ __forceinline__ void cp_commit() { asm volatile("cp.async.commit_group;" ::: "memory"); }
__device__ __forceinline__ void cp_wait1()  { asm volatile("cp.async.wait_group 1;" ::: "memory"); }

__device__ __forceinline__ void ldsm4(u32& r0, u32& r1, u32& r2, u32& r3, u32 addr) {
    asm volatile("ldmatrix.sync.aligned.m8n8.x4.shared.b16 {%0,%1,%2,%3}, [%4];"
                 : "=r"(r0), "=r"(r1), "=r"(r2), "=r"(r3) : "r"(addr));
}
__device__ __forceinline__ void mma16816(float* c, const u32* a, const u32* b) {
    asm volatile("mma.sync.aligned.m16n8k16.row.col.f32.f16.f16.f32 "
                 "{%0,%1,%2,%3}, {%4,%5,%6,%7}, {%8,%9}, {%0,%1,%2,%3};"
                 : "+f"(c[0]), "+f"(c[1]), "+f"(c[2]), "+f"(c[3])
                 : "r"(a[0]), "r"(a[1]), "r"(a[2]), "r"(a[3]), "r"(b[0]), "r"(b[1]));
}

__device__ __forceinline__ u32 swz128(u32 off) { return off ^ ((off >> 3) & 0x70); }

// ---------------- prep / zero kernels ----------------------------------------
__global__ void prep_kernel(const float* __restrict__ x,
                            const float* __restrict__ W,
                            const float* __restrict__ centers,
                            const float* __restrict__ bias) {
    int b = blockIdx.x;
    if (b < 4096) {
        int gw   = b * 8 + (threadIdx.x >> 5);
        int lane = threadIdx.x & 31;
        int e = gw >> 11;
        const float4* wr = (const float4*)(W + (size_t)gw * ND);
        const float4* cr = (const float4*)(centers + (size_t)e * ND);
        __half2* ph = (__half2*)(g_wh + (size_t)gw * ND);
        float s = 0.f;
#pragma unroll
        for (int i = 0; i < ND / 128; i++) {
            int idx = lane + 32 * i;
            float4 w4 = wr[idx];
            float4 c4 = cr[idx];
            s += w4.x * c4.x + w4.y * c4.y + w4.z * c4.z + w4.w * c4.w;
            ph[2 * idx]     = __half2(__float2half_rn(w4.x), __float2half_rn(w4.y));
            ph[2 * idx + 1] = __half2(__float2half_rn(w4.z), __float2half_rn(w4.w));
        }
#pragma unroll
        for (int o = 16; o; o >>= 1) s += __shfl_xor_sync(0xffffffffu, s, o);
        if (lane == 0) g_dcomb[gw] = bias[gw] - s;
    } else {
        int i = (b - 4096) * 256 + threadIdx.x;
        float4 v = ((const float4*)x)[i];
        __half2* ph = (__half2*)g_xh;
        ph[2 * i]     = __half2(__float2half_rn(v.x), __float2half_rn(v.y));
        ph[2 * i + 1] = __half2(__float2half_rn(v.z), __float2half_rn(v.w));
    }
}

__global__ void zero_out_kernel(float4* __restrict__ out) {
    out[blockIdx.x * 256 + threadIdx.x] = make_float4(0.f, 0.f, 0.f, 0.f);
}

// ---------------- main GEMM kernel -------------------------------------------
// grid (NH/128, NB/128, 2) = 1024 CTAs; 256 threads, 8 warps (2m x 4n of 64x32).
// blockIdx.z selects experts [8z, 8z+8). 64 chunks = 8 experts x 8 k-chunks;
// 2 chunks per barrier; fragment ping-pong across the intra-pair boundary.
// Results atomically accumulated into out (pre-zeroed).

__device__ __forceinline__ void load_chunk(int gc, u32 dst, int mb, int hb,
                                           int ebase, int tid) {
    int e = ebase + (gc >> 3), kc = (gc & 7) * KC;
    int row = tid >> 3, c = tid & 7;
    u32 so = swz128((u32)(row * 128 + c * 16));
    const __half* pxh = g_xh + (size_t)(mb + row) * ND + kc + c * 8;
    const __half* pwh = g_wh + (size_t)(e * NH + hb + row) * ND + kc + c * 8;
#pragma unroll
    for (int i = 0; i < 4; i++) {
        u32 d = dst + so + (u32)i * 4096;          // +32 rows per step
        size_t eo = (size_t)(32 * i) * ND;
        cp16(d + 0 * TILE, pxh + eo);
        cp16(d + 1 * TILE, pwh + eo);
    }
}

__device__ __forceinline__ void load_frags(int ks, u32 Ah, u32 Bh, int wm, int wn,
                                           int lane, u32 ah[4][4], u32 bh[4][2]) {
    u32 arel = swz128((u32)((lane & 15) * 128 + ks * 32 + (lane >> 4) * 16));
#pragma unroll
    for (int mt = 0; mt < 4; mt++) {
        u32 ao = (u32)((wm + mt * 16) * 128) + arel;
        ldsm4(ah[mt][0], ah[mt][1], ah[mt][2], ah[mt][3], Ah + ao);
    }
    u32 brel = swz128((u32)((lane & 7) * 128 + ks * 32 + ((lane >> 3) & 1) * 16));
#pragma unroll
    for (int pr = 0; pr < 2; pr++) {
        u32 bo = (u32)((wn + pr * 16 + ((lane >> 4) & 1) * 8) * 128) + brel;
        ldsm4(bh[pr * 2][0], bh[pr * 2][1], bh[pr * 2 + 1][0], bh[pr * 2 + 1][1], Bh + bo);
    }
}

__global__ void __launch_bounds__(256, 1)
gemm_kernel(float* __restrict__ out) {
    extern __shared__ char smem[];
    float* dsm = (float*)smem;                     // [8][128] combined bias
    u32 sb = smem_u32(smem) + OFF_STAGES;
    const int tid = threadIdx.x, wid = tid >> 5, lane = tid & 31;
    const int hb = blockIdx.x * 128, mb = blockIdx.y * 128;
    const int ebase = blockIdx.z * 8;
    const int wm = (wid >> 2) * 64, wn = (wid & 3) * 32;

    // stage this CTA's 8-expert combined-bias slice
#pragma unroll
    for (int i = tid; i < 8 * 128; i += 256)
        dsm[i] = g_dcomb[(size_t)(ebase + (i >> 7)) * NH + hb + (i & 127)];

    // prologue: group G0 = chunks 0,1; G1 = chunks 2,3
    load_chunk(0, sb + 0 * STAGE, mb, hb, ebase, tid);
    load_chunk(1, sb + 1 * STAGE, mb, hb, ebase, tid); cp_commit();
    load_chunk(2, sb + 2 * STAGE, mb, hb, ebase, tid);
    load_chunk(3, sb + 3 * STAGE, mb, hb, ebase, tid); cp_commit();

    float acc[4][4][4], oacc[4][4][4];
#pragma unroll
    for (int a = 0; a < 4; a++)
#pragma unroll
        for (int b = 0; b < 4; b++)
#pragma unroll
            for (int c = 0; c < 4; c++) { acc[a][b][c] = 0.f; oacc[a][b][c] = 0.f; }

    u32 ah[2][4][4], bh[2][4][2];

    for (int j = 0; j < 32; j++) {     // iteration = chunk pair (2j, 2j+1)
        int c0 = 2 * j;
        cp_wait1();                    // groups up to G_j complete
        __syncthreads();

        u32 s0 = sb + (u32)(c0 % NSTAGE) * STAGE;
        u32 s1 = sb + (u32)((c0 + 1) % NSTAGE) * STAGE;
        u32 A0 = s0, B0 = s0 + TILE, A1 = s1, B1 = s1 + TILE;

        load_frags(0, A0, B0, wm, wn, lane, ah[0], bh[0]);

        if (c0 + 4 < 64) {             // prefetch group j+2 = chunks 2j+4, 2j+5
            load_chunk(c0 + 4, sb + (u32)((c0 + 4) % NSTAGE) * STAGE, mb, hb, ebase, tid);
            load_chunk(c0 + 5, sb + (u32)((c0 + 5) % NSTAGE) * STAGE, mb, hb, ebase, tid);
        }
        cp_commit();

        // chunk c0: at ks3 preload chunk c1's ks0 (same barrier scope)
#pragma unroll
        for (int ks = 0; ks < 4; ks++) {
            int cur = ks & 1;
            if (ks < 3) load_frags(ks + 1, A0, B0, wm, wn, lane, ah[cur ^ 1], bh[cur ^ 1]);
            else        load_frags(0,      A1, B1, wm, wn, lane, ah[cur ^ 1], bh[cur ^ 1]);
#pragma unroll
            for (int mt = 0; mt < 4; mt++)
#pragma unroll
                for (int nt = 0; nt < 4; nt++)
                    mma16816(acc[mt][nt], ah[cur][mt], bh[cur][nt]);
        }

        // chunk c1
#pragma unroll
        for (int ks = 0; ks < 4; ks++) {
            int cur = ks & 1;
            if (ks < 3) load_frags(ks + 1, A1, B1, wm, wn, lane, ah[cur ^ 1], bh[cur ^ 1]);
#pragma unroll
            for (int mt = 0; mt < 4; mt++)
#pragma unroll
                for (int nt = 0; nt < 4; nt++)
                    mma16816(acc[mt][nt], ah[cur][mt], bh[cur][nt]);
        }

        if ((j & 3) == 3) {            // finished local expert j>>2: relu + accumulate
            int el = j >> 2;
            const float2* dp = (const float2*)(dsm + el * 128 + wn);
#pragma unroll
            for (int nt = 0; nt < 4; nt++) {
                float2 d2 = dp[nt * 4 + (lane & 3)];
#pragma unroll
                for (int mt = 0; mt < 4; mt++) {
                    oacc[mt][nt][0] += fmaxf(acc[mt][nt][0] + d2.x, 0.f);
                    oacc[mt][nt][1] += fmaxf(acc[mt][nt][1] + d2.y, 0.f);
                    oacc[mt][nt][2] += fmaxf(acc[mt][nt][2] + d2.x, 0.f);
                    oacc[mt][nt][3] += fmaxf(acc[mt][nt][3] + d2.y, 0.f);
                    acc[mt][nt][0] = 0.f; acc[mt][nt][1] = 0.f;
                    acc[mt][nt][2] = 0.f; acc[mt][nt][3] = 0.f;
                }
            }
        }
    }

    // accumulate this half's relu-sum into out (pre-zeroed)
#pragma unroll
    for (int mt = 0; mt < 4; mt++)
#pragma unroll
        for (int nt = 0; nt < 4; nt++) {
            int r0 = mb + wm + mt * 16 + (lane >> 2);
            int cc = hb + wn + nt * 8 + 2 * (lane & 3);
            float* p0 = out + (size_t)r0 * NH + cc;
            float* p1 = out + (size_t)(r0 + 8) * NH + cc;
            atomicAdd(p0,     oacc[mt][nt][0]);
            atomicAdd(p0 + 1, oacc[mt][nt][1]);
            atomicAdd(p1,     oacc[mt][nt][2]);
            atomicAdd(p1 + 1, oacc[mt][nt][3]);
        }
}

// ---------------- launch -----------------------------------------------------
extern "C" void kernel_launch(void* const* d_in, const int* in_sizes, int n_in,
                              void* d_out, int out_size) {
    const float* x       = (const float*)d_in[0];  // [B, D]
    const float* centers = (const float*)d_in[1];  // [E, D]
    const float* W       = (const float*)d_in[2];  // [E, H, D]
    const float* bias    = (const float*)d_in[3];  // [E, H]
    float* out = (float*)d_out;                    // [B, H]

    cudaFuncSetAttribute(gemm_kernel, cudaFuncAttributeMaxDynamicSharedMemorySize, SMEM_TOTAL);

    prep_kernel<<<4096 + 2048, 256>>>(x, W, centers, bias);
    zero_out_kernel<<<(NB * NH / 4) / 256, 256>>>((float4*)out);

    dim3 grid(NH / 128, NB / 128, 2);   // 1024 CTAs
    gemm_kernel<<<grid, 256, SMEM_TOTAL>>>(out);
}

// round 14
// speedup vs baseline: 2.2815x; 1.0111x over previous
#include <cuda_runtime.h>
#include <cuda_fp16.h>
#include <cstdint>

typedef unsigned long long u64;
typedef uint32_t u32;

#define NB 4096
#define NE 16
#define ND 512
#define NH 2048

#define KC 64                          // k-chunk: 64 fp16 = 128B rows
#define TILE 16384                     // 128 x 64 fp16 tile bytes
#define STAGE (2 * TILE)               // x tile + w tile per chunk
#define NSTAGE 6
#define OFF_STAGES 4096                // after d-table (8*128 floats)
#define SMEM_TOTAL (OFF_STAGES + NSTAGE * STAGE)   // 200704 B

// ---------------- scratch (device globals; no allocations allowed) ----------
__device__ __half g_xh[NB * ND];
__device__ __half g_wh[NE * NH * ND];
__device__ float  g_dcomb[NE * NH];

// ---------------- PTX helpers ----------------------------------------------
__device__ __forceinline__ u32 smem_u32(const void* p) {
    u32 a;
    asm("{ .reg .u64 t; cvta.to.shared.u64 t, %1; cvt.u32.u64 %0, t; }" : "=r"(a) : "l"(p));
    return a;
}
__device__ __forceinline__ void cp16(u32 dst, const void* src) {
    asm volatile("cp.async.cg.shared.global [%0], [%1], 16;" :: "r"(dst), "l"(src) : "memory");
}
__device__ __forceinline__ void cp_commit() { asm volatile("cp.async.commit_group;" ::: "memory"); }
__device__ __forceinline__ void cp_wait1()  { asm volatile("cp.async.wait_group 1;" ::: "memory"); }

__device__ __forceinline__ void ldsm4(u32& r0, u32& r1, u32& r2, u32& r3, u32 addr) {
    asm volatile("ldmatrix.sync.aligned.m8n8.x4.shared.b16 {%0,%1,%2,%3}, [%4];"
                 : "=r"(r0), "=r"(r1), "=r"(r2), "=r"(r3) : "r"(addr));
}
__device__ __forceinline__ void mma16816(float* c, const u32* a, const u32* b) {
    asm volatile("mma.sync.aligned.m16n8k16.row.col.f32.f16.f16.f32 "
                 "{%0,%1,%2,%3}, {%4,%5,%6,%7}, {%8,%9}, {%0,%1,%2,%3};"
                 : "+f"(c[0]), "+f"(c[1]), "+f"(c[2]), "+f"(c[3])
                 : "r"(a[0]), "r"(a[1]), "r"(a[2]), "r"(a[3]), "r"(b[0]), "r"(b[1]));
}

__device__ __forceinline__ u32 swz128(u32 off) { return off ^ ((off >> 3) & 0x70); }

__device__ __forceinline__ u32 h2u(__half2 h) { return *(u32*)&h; }

// ---------------- fused prep + zero kernel -----------------------------------
// blocks [0, 4096):      W rows -> fp16 (16B stores) + d = bias - c_e.W_row
// blocks [4096, 5120):   x -> fp16 (16B stores)
// blocks [5120, 13312):  zero out
__global__ void prep_kernel(const float* __restrict__ x,
                            const float* __restrict__ W,
                            const float* __restrict__ centers,
                            const float* __restrict__ bias,
                            float4* __restrict__ out) {
    int b = blockIdx.x;
    if (b < 4096) {
        int gw   = b * 8 + (threadIdx.x >> 5);
        int lane = threadIdx.x & 31;
        int e = gw >> 11;
        const float4* wr = (const float4*)(W + (size_t)gw * ND);
        const float4* cr = (const float4*)(centers + (size_t)e * ND);
        uint4* ph = (uint4*)(g_wh + (size_t)gw * ND);
        float s = 0.f;
#pragma unroll
        for (int i = 0; i < 2; i++) {
            int q = lane + 32 * i;          // uint4 (8-half) index, 0..63
            float4 wa = wr[2 * q], wb = wr[2 * q + 1];
            float4 ca = cr[2 * q], cb = cr[2 * q + 1];
            s += wa.x * ca.x + wa.y * ca.y + wa.z * ca.z + wa.w * ca.w
               + wb.x * cb.x + wb.y * cb.y + wb.z * cb.z + wb.w * cb.w;
            uint4 h;
            h.x = h2u(__floats2half2_rn(wa.x, wa.y));
            h.y = h2u(__floats2half2_rn(wa.z, wa.w));
            h.z = h2u(__floats2half2_rn(wb.x, wb.y));
            h.w = h2u(__floats2half2_rn(wb.z, wb.w));
            ph[q] = h;
        }
#pragma unroll
        for (int o = 16; o; o >>= 1) s += __shfl_xor_sync(0xffffffffu, s, o);
        if (lane == 0) g_dcomb[gw] = bias[gw] - s;
    } else if (b < 5120) {
        int i = (b - 4096) * 256 + threadIdx.x;   // 8-float group index
        const float4* xr = (const float4*)x;
        float4 a = xr[2 * i], c = xr[2 * i + 1];
        uint4 h;
        h.x = h2u(__floats2half2_rn(a.x, a.y));
        h.y = h2u(__floats2half2_rn(a.z, a.w));
        h.z = h2u(__floats2half2_rn(c.x, c.y));
        h.w = h2u(__floats2half2_rn(c.z, c.w));
        ((uint4*)g_xh)[i] = h;
    } else {
        out[(size_t)(b - 5120) * 256 + threadIdx.x] = make_float4(0.f, 0.f, 0.f, 0.f);
    }
}

// ---------------- main GEMM kernel -------------------------------------------
// grid (NH/128, NB/128, 2) = 1024 CTAs; 256 threads, 8 warps (2m x 4n of 64x32).
// blockIdx.z selects experts [8z, 8z+8). 64 chunks = 8 experts x 8 k-chunks;
// 2 chunks per barrier; fragment ping-pong across the intra-pair boundary.
// Results atomically accumulated into out (pre-zeroed by prep).

__device__ __forceinline__ void load_chunk(int gc, u32 dst, int mb, int hb,
                                           int ebase, int tid) {
    int e = ebase + (gc >> 3), kc = (gc & 7) * KC;
    int row = tid >> 3, c = tid & 7;
    u32 so = swz128((u32)(row * 128 + c * 16));
    const __half* pxh = g_xh + (size_t)(mb + row) * ND + kc + c * 8;
    const __half* pwh = g_wh + (size_t)(e * NH + hb + row) * ND + kc + c * 8;
#pragma unroll
    for (int i = 0; i < 4; i++) {
        u32 d = dst + so + (u32)i * 4096;          // +32 rows per step
        size_t eo = (size_t)(32 * i) * ND;
        cp16(d + 0 * TILE, pxh + eo);
        cp16(d + 1 * TILE, pwh + eo);
    }
}

__device__ __forceinline__ void load_frags(int ks, u32 Ah, u32 Bh, int wm, int wn,
                                           int lane, u32 ah[4][4], u32 bh[4][2]) {
    u32 arel = swz128((u32)((lane & 15) * 128 + ks * 32 + (lane >> 4) * 16));
#pragma unroll
    for (int mt = 0; mt < 4; mt++) {
        u32 ao = (u32)((wm + mt * 16) * 128) + arel;
        ldsm4(ah[mt][0], ah[mt][1], ah[mt][2], ah[mt][3], Ah + ao);
    }
    u32 brel = swz128((u32)((lane & 7) * 128 + ks * 32 + ((lane >> 3) & 1) * 16));
#pragma unroll
    for (int pr = 0; pr < 2; pr++) {
        u32 bo = (u32)((wn + pr * 16 + ((lane >> 4) & 1) * 8) * 128) + brel;
        ldsm4(bh[pr * 2][0], bh[pr * 2][1], bh[pr * 2 + 1][0], bh[pr * 2 + 1][1], Bh + bo);
    }
}

__global__ void __launch_bounds__(256, 1)
gemm_kernel(float* __restrict__ out) {
    extern __shared__ char smem[];
    float* dsm = (float*)smem;                     // [8][128] combined bias
    u32 sb = smem_u32(smem) + OFF_STAGES;
    const int tid = threadIdx.x, wid = tid >> 5, lane = tid & 31;
    const int hb = blockIdx.x * 128, mb = blockIdx.y * 128;
    const int ebase = blockIdx.z * 8;
    const int wm = (wid >> 2) * 64, wn = (wid & 3) * 32;

    // stage this CTA's 8-expert combined-bias slice
#pragma unroll
    for (int i = tid; i < 8 * 128; i += 256)
        dsm[i] = g_dcomb[(size_t)(ebase + (i >> 7)) * NH + hb + (i & 127)];

    // prologue: group G0 = chunks 0,1; G1 = chunks 2,3
    load_chunk(0, sb + 0 * STAGE, mb, hb, ebase, tid);
    load_chunk(1, sb + 1 * STAGE, mb, hb, ebase, tid); cp_commit();
    load_chunk(2, sb + 2 * STAGE, mb, hb, ebase, tid);
    load_chunk(3, sb + 3 * STAGE, mb, hb, ebase, tid); cp_commit();

    float acc[4][4][4], oacc[4][4][4];
#pragma unroll
    for (int a = 0; a < 4; a++)
#pragma unroll
        for (int b = 0; b < 4; b++)
#pragma unroll
            for (int c = 0; c < 4; c++) { acc[a][b][c] = 0.f; oacc[a][b][c] = 0.f; }

    u32 ah[2][4][4], bh[2][4][2];
    float2 dreg[4];

    for (int j = 0; j < 32; j++) {     // iteration = chunk pair (2j, 2j+1)
        int c0 = 2 * j;
        cp_wait1();                    // groups up to G_j complete
        __syncthreads();

        u32 s0 = sb + (u32)(c0 % NSTAGE) * STAGE;
        u32 s1 = sb + (u32)((c0 + 1) % NSTAGE) * STAGE;
        u32 A0 = s0, B0 = s0 + TILE, A1 = s1, B1 = s1 + TILE;

        load_frags(0, A0, B0, wm, wn, lane, ah[0], bh[0]);

        if (c0 + 4 < 64) {             // prefetch group j+2 = chunks 2j+4, 2j+5
            load_chunk(c0 + 4, sb + (u32)((c0 + 4) % NSTAGE) * STAGE, mb, hb, ebase, tid);
            load_chunk(c0 + 5, sb + (u32)((c0 + 5) % NSTAGE) * STAGE, mb, hb, ebase, tid);
        }
        cp_commit();

        // prefetch the epilogue bias one pair early (off the critical path)
        if ((j & 3) == 2) {
            const float2* dp = (const float2*)(dsm + (j >> 2) * 128 + wn);
#pragma unroll
            for (int nt = 0; nt < 4; nt++) dreg[nt] = dp[nt * 4 + (lane & 3)];
        }

        // chunk c0: at ks3 preload chunk c1's ks0 (same barrier scope)
#pragma unroll
        for (int ks = 0; ks < 4; ks++) {
            int cur = ks & 1;
            if (ks < 3) load_frags(ks + 1, A0, B0, wm, wn, lane, ah[cur ^ 1], bh[cur ^ 1]);
            else        load_frags(0,      A1, B1, wm, wn, lane, ah[cur ^ 1], bh[cur ^ 1]);
#pragma unroll
            for (int mt = 0; mt < 4; mt++)
#pragma unroll
                for (int nt = 0; nt < 4; nt++)
                    mma16816(acc[mt][nt], ah[cur][mt], bh[cur][nt]);
        }

        // chunk c1
#pragma unroll
        for (int ks = 0; ks < 4; ks++) {
            int cur = ks & 1;
            if (ks < 3) load_frags(ks + 1, A1, B1, wm, wn, lane, ah[cur ^ 1], bh[cur ^ 1]);
#pragma unroll
            for (int mt = 0; mt < 4; mt++)
#pragma unroll
                for (int nt = 0; nt < 4; nt++)
                    mma16816(acc[mt][nt], ah[cur][mt], bh[cur][nt]);
        }

        if ((j & 3) == 3) {            // finished local expert: relu + accumulate
#pragma unroll
            for (int nt = 0; nt < 4; nt++) {
                float2 d2 = dreg[nt];
#pragma unroll
                for (int mt = 0; mt < 4; mt++) {
                    oacc[mt][nt][0] += fmaxf(acc[mt][nt][0] + d2.x, 0.f);
                    oacc[mt][nt][1] += fmaxf(acc[mt][nt][1] + d2.y, 0.f);
                    oacc[mt][nt][2] += fmaxf(acc[mt][nt][2] + d2.x, 0.f);
                    oacc[mt][nt][3] += fmaxf(acc[mt][nt][3] + d2.y, 0.f);
                    acc[mt][nt][0] = 0.f; acc[mt][nt][1] = 0.f;
                    acc[mt][nt][2] = 0.f; acc[mt][nt][3] = 0.f;
                }
            }
        }
    }

    // accumulate this half's relu-sum into out (pre-zeroed)
#pragma unroll
    for (int mt = 0; mt < 4; mt++)
#pragma unroll
        for (int nt = 0; nt < 4; nt++) {
            int r0 = mb + wm + mt * 16 + (lane >> 2);
            int cc = hb + wn + nt * 8 + 2 * (lane & 3);
            float* p0 = out + (size_t)r0 * NH + cc;
            float* p1 = out + (size_t)(r0 + 8) * NH + cc;
            atomicAdd(p0,     oacc[mt][nt][0]);
            atomicAdd(p0 + 1, oacc[mt][nt][1]);
            atomicAdd(p1,     oacc[mt][nt][2]);
            atomicAdd(p1 + 1, oacc[mt][nt][3]);
        }
}

// ---------------- launch -----------------------------------------------------
extern "C" void kernel_launch(void* const* d_in, const int* in_sizes, int n_in,
                              void* d_out, int out_size) {
    const float* x       = (const float*)d_in[0];  // [B, D]
    const float* centers = (const float*)d_in[1];  // [E, D]
    const float* W       = (const float*)d_in[2];  // [E, H, D]
    const float* bias    = (const float*)d_in[3];  // [E, H]
    float* out = (float*)d_out;                    // [B, H]

    cudaFuncSetAttribute(gemm_kernel, cudaFuncAttributeMaxDynamicSharedMemorySize, SMEM_TOTAL);

    // 4096 W blocks + 1024 x blocks + 8192 zero blocks
    prep_kernel<<<4096 + 1024 + 8192, 256>>>(x, W, centers, bias, (float4*)out);

    dim3 grid(NH / 128, NB / 128, 2);   // 1024 CTAs
    gemm_kernel<<<grid, 256, SMEM_TOTAL>>>(out);
}

// round 15
// speedup vs baseline: 2.3053x; 1.0104x over previous
#include <cuda_runtime.h>
#include <cuda_fp16.h>
#include <cstdint>

typedef unsigned long long u64;
typedef uint32_t u32;

#define NB 4096
#define NE 16
#define ND 512
#define NH 2048

#define KC 64                          // k-chunk: 64 fp16 = 128B rows
#define TILE 16384                     // 128 x 64 fp16 tile bytes
#define STAGE (2 * TILE)               // x tile + w tile per chunk
#define NSTAGE 6
#define OFF_STAGES 4096                // after d-table (8*128 floats)
#define SMEM_TOTAL (OFF_STAGES + NSTAGE * STAGE)   // 200704 B

// ---------------- scratch (device globals; no allocations allowed) ----------
__device__ __half g_xh[NB * ND];
__device__ __half g_wh[NE * NH * ND];
__device__ float  g_dcomb[NE * NH];

// ---------------- PTX helpers ----------------------------------------------
__device__ __forceinline__ u32 smem_u32(const void* p) {
    u32 a;
    asm("{ .reg .u64 t; cvta.to.shared.u64 t, %1; cvt.u32.u64 %0, t; }" : "=r"(a) : "l"(p));
    return a;
}
__device__ __forceinline__ void cp16(u32 dst, const void* src) {
    asm volatile("cp.async.cg.shared.global [%0], [%1], 16;" :: "r"(dst), "l"(src) : "memory");
}
__device__ __forceinline__ void cp_commit() { asm volatile("cp.async.commit_group;" ::: "memory"); }
__device__ __forceinline__ void cp_wait1()  { asm volatile("cp.async.wait_group 1;" ::: "memory"); }

__device__ __forceinline__ void ldsm4(u32& r0, u32& r1, u32& r2, u32& r3, u32 addr) {
    asm volatile("ldmatrix.sync.aligned.m8n8.x4.shared.b16 {%0,%1,%2,%3}, [%4];"
                 : "=r"(r0), "=r"(r1), "=r"(r2), "=r"(r3) : "r"(addr));
}
__device__ __forceinline__ void mma16816(float* c, const u32* a, const u32* b) {
    asm volatile("mma.sync.aligned.m16n8k16.row.col.f32.f16.f16.f32 "
                 "{%0,%1,%2,%3}, {%4,%5,%6,%7}, {%8,%9}, {%0,%1,%2,%3};"
                 : "+f"(c[0]), "+f"(c[1]), "+f"(c[2]), "+f"(c[3])
                 : "r"(a[0]), "r"(a[1]), "r"(a[2]), "r"(a[3]), "r"(b[0]), "r"(b[1]));
}

__device__ __forceinline__ u32 swz128(u32 off) { return off ^ ((off >> 3) & 0x70); }

__device__ __forceinline__ u32 h2u(__half2 h) { return *(u32*)&h; }

// ---------------- fused prep + zero kernel -----------------------------------
// blocks [0, 4096):      W rows -> fp16 (16B stores) + d = bias - c_e.W_row
// blocks [4096, 5120):   x -> fp16 (16B stores)
// blocks [5120, 13312):  zero out
__global__ void prep_kernel(const float* __restrict__ x,
                            const float* __restrict__ W,
                            const float* __restrict__ centers,
                            const float* __restrict__ bias,
                            float4* __restrict__ out) {
    int b = blockIdx.x;
    if (b < 4096) {
        int gw   = b * 8 + (threadIdx.x >> 5);
        int lane = threadIdx.x & 31;
        int e = gw >> 11;
        const float4* wr = (const float4*)(W + (size_t)gw * ND);
        const float4* cr = (const float4*)(centers + (size_t)e * ND);
        uint4* ph = (uint4*)(g_wh + (size_t)gw * ND);
        float s = 0.f;
#pragma unroll
        for (int i = 0; i < 2; i++) {
            int q = lane + 32 * i;          // uint4 (8-half) index, 0..63
            float4 wa = wr[2 * q], wb = wr[2 * q + 1];
            float4 ca = cr[2 * q], cb = cr[2 * q + 1];
            s += wa.x * ca.x + wa.y * ca.y + wa.z * ca.z + wa.w * ca.w
               + wb.x * cb.x + wb.y * cb.y + wb.z * cb.z + wb.w * cb.w;
            uint4 h;
            h.x = h2u(__floats2half2_rn(wa.x, wa.y));
            h.y = h2u(__floats2half2_rn(wa.z, wa.w));
            h.z = h2u(__floats2half2_rn(wb.x, wb.y));
            h.w = h2u(__floats2half2_rn(wb.z, wb.w));
            ph[q] = h;
        }
#pragma unroll
        for (int o = 16; o; o >>= 1) s += __shfl_xor_sync(0xffffffffu, s, o);
        if (lane == 0) g_dcomb[gw] = bias[gw] - s;
    } else if (b < 5120) {
        int i = (b - 4096) * 256 + threadIdx.x;   // 8-float group index
        const float4* xr = (const float4*)x;
        float4 a = xr[2 * i], c = xr[2 * i + 1];
        uint4 h;
        h.x = h2u(__floats2half2_rn(a.x, a.y));
        h.y = h2u(__floats2half2_rn(a.z, a.w));
        h.z = h2u(__floats2half2_rn(c.x, c.y));
        h.w = h2u(__floats2half2_rn(c.z, c.w));
        ((uint4*)g_xh)[i] = h;
    } else {
        out[(size_t)(b - 5120) * 256 + threadIdx.x] = make_float4(0.f, 0.f, 0.f, 0.f);
    }
}

// ---------------- main GEMM kernel -------------------------------------------
// grid (NH/128, NB/128, 2) = 1024 CTAs; 256 threads, 8 warps (2m x 4n of 64x32).
// blockIdx.z selects experts [8z, 8z+8). 64 chunks = 8 experts x 8 k-chunks;
// 2 chunks per barrier; fragment ping-pong across the intra-pair boundary.
// Pair-start reordered: ks0 frags + first MMA block issue BEFORE the cp.async
// prefetch burst, so LDGSTS issue rides in the MMA shadow.

__device__ __forceinline__ void load_chunk(int gc, u32 dst, int mb, int hb,
                                           int ebase, int tid) {
    int e = ebase + (gc >> 3), kc = (gc & 7) * KC;
    int row = tid >> 3, c = tid & 7;
    u32 so = swz128((u32)(row * 128 + c * 16));
    const __half* pxh = g_xh + (size_t)(mb + row) * ND + kc + c * 8;
    const __half* pwh = g_wh + (size_t)(e * NH + hb + row) * ND + kc + c * 8;
#pragma unroll
    for (int i = 0; i < 4; i++) {
        u32 d = dst + so + (u32)i * 4096;          // +32 rows per step
        size_t eo = (size_t)(32 * i) * ND;
        cp16(d + 0 * TILE, pxh + eo);
        cp16(d + 1 * TILE, pwh + eo);
    }
}

__device__ __forceinline__ void load_frags(int ks, u32 Ah, u32 Bh, int wm, int wn,
                                           int lane, u32 ah[4][4], u32 bh[4][2]) {
    u32 arel = swz128((u32)((lane & 15) * 128 + ks * 32 + (lane >> 4) * 16));
#pragma unroll
    for (int mt = 0; mt < 4; mt++) {
        u32 ao = (u32)((wm + mt * 16) * 128) + arel;
        ldsm4(ah[mt][0], ah[mt][1], ah[mt][2], ah[mt][3], Ah + ao);
    }
    u32 brel = swz128((u32)((lane & 7) * 128 + ks * 32 + ((lane >> 3) & 1) * 16));
#pragma unroll
    for (int pr = 0; pr < 2; pr++) {
        u32 bo = (u32)((wn + pr * 16 + ((lane >> 4) & 1) * 8) * 128) + brel;
        ldsm4(bh[pr * 2][0], bh[pr * 2][1], bh[pr * 2 + 1][0], bh[pr * 2 + 1][1], Bh + bo);
    }
}

#define MMA_BLOCK(buf)                                                       \
    _Pragma("unroll")                                                        \
    for (int mt = 0; mt < 4; mt++)                                           \
        _Pragma("unroll")                                                    \
        for (int nt = 0; nt < 4; nt++)                                       \
            mma16816(acc[mt][nt], ah[buf][mt], bh[buf][nt]);

__global__ void __launch_bounds__(256, 1)
gemm_kernel(float* __restrict__ out) {
    extern __shared__ char smem[];
    float* dsm = (float*)smem;                     // [8][128] combined bias
    u32 sb = smem_u32(smem) + OFF_STAGES;
    const int tid = threadIdx.x, wid = tid >> 5, lane = tid & 31;
    const int hb = blockIdx.x * 128, mb = blockIdx.y * 128;
    const int ebase = blockIdx.z * 8;
    const int wm = (wid >> 2) * 64, wn = (wid & 3) * 32;

    // stage this CTA's 8-expert combined-bias slice
#pragma unroll
    for (int i = tid; i < 8 * 128; i += 256)
        dsm[i] = g_dcomb[(size_t)(ebase + (i >> 7)) * NH + hb + (i & 127)];

    // prologue: group G0 = chunks 0,1; G1 = chunks 2,3
    load_chunk(0, sb + 0 * STAGE, mb, hb, ebase, tid);
    load_chunk(1, sb + 1 * STAGE, mb, hb, ebase, tid); cp_commit();
    load_chunk(2, sb + 2 * STAGE, mb, hb, ebase, tid);
    load_chunk(3, sb + 3 * STAGE, mb, hb, ebase, tid); cp_commit();

    float acc[4][4][4], oacc[4][4][4];
#pragma unroll
    for (int a = 0; a < 4; a++)
#pragma unroll
        for (int b = 0; b < 4; b++)
#pragma unroll
            for (int c = 0; c < 4; c++) { acc[a][b][c] = 0.f; oacc[a][b][c] = 0.f; }

    u32 ah[2][4][4], bh[2][4][2];
    float2 dreg[4];

    for (int j = 0; j < 32; j++) {     // iteration = chunk pair (2j, 2j+1)
        int c0 = 2 * j;
        cp_wait1();                    // groups up to G_j complete
        __syncthreads();

        u32 s0 = sb + (u32)(c0 % NSTAGE) * STAGE;
        u32 s1 = sb + (u32)((c0 + 1) % NSTAGE) * STAGE;
        u32 A0 = s0, B0 = s0 + TILE, A1 = s1, B1 = s1 + TILE;

        // ---- chunk c0, ks0: frags + MMAs FIRST (LDGSTS burst deferred) ----
        load_frags(0, A0, B0, wm, wn, lane, ah[0], bh[0]);
        load_frags(1, A0, B0, wm, wn, lane, ah[1], bh[1]);
        MMA_BLOCK(0)

        // ---- now the global->smem prefetch rides in the MMA shadow ----
        if (c0 + 4 < 64) {             // prefetch group j+2 = chunks 2j+4, 2j+5
            load_chunk(c0 + 4, sb + (u32)((c0 + 4) % NSTAGE) * STAGE, mb, hb, ebase, tid);
            load_chunk(c0 + 5, sb + (u32)((c0 + 5) % NSTAGE) * STAGE, mb, hb, ebase, tid);
        }
        cp_commit();

        // prefetch the epilogue bias one pair early (off the critical path)
        if ((j & 3) == 2) {
            const float2* dp = (const float2*)(dsm + (j >> 2) * 128 + wn);
#pragma unroll
            for (int nt = 0; nt < 4; nt++) dreg[nt] = dp[nt * 4 + (lane & 3)];
        }

        // ---- chunk c0, ks1..3 (at ks3 preload chunk c1's ks0) ----
        load_frags(2, A0, B0, wm, wn, lane, ah[0], bh[0]);
        MMA_BLOCK(1)
        load_frags(3, A0, B0, wm, wn, lane, ah[1], bh[1]);
        MMA_BLOCK(0)
        load_frags(0, A1, B1, wm, wn, lane, ah[0], bh[0]);
        MMA_BLOCK(1)

        // ---- chunk c1 ----
#pragma unroll
        for (int ks = 0; ks < 4; ks++) {
            int cur = ks & 1;
            if (ks < 3) load_frags(ks + 1, A1, B1, wm, wn, lane, ah[cur ^ 1], bh[cur ^ 1]);
            MMA_BLOCK(cur)
        }

        if ((j & 3) == 3) {            // finished local expert: relu + accumulate
#pragma unroll
            for (int nt = 0; nt < 4; nt++) {
                float2 d2 = dreg[nt];
#pragma unroll
                for (int mt = 0; mt < 4; mt++) {
                    oacc[mt][nt][0] += fmaxf(acc[mt][nt][0] + d2.x, 0.f);
                    oacc[mt][nt][1] += fmaxf(acc[mt][nt][1] + d2.y, 0.f);
                    oacc[mt][nt][2] += fmaxf(acc[mt][nt][2] + d2.x, 0.f);
                    oacc[mt][nt][3] += fmaxf(acc[mt][nt][3] + d2.y, 0.f);
                    acc[mt][nt][0] = 0.f; acc[mt][nt][1] = 0.f;
                    acc[mt][nt][2] = 0.f; acc[mt][nt][3] = 0.f;
                }
            }
        }
    }

    // accumulate this half's relu-sum into out (pre-zeroed)
#pragma unroll
    for (int mt = 0; mt < 4; mt++)
#pragma unroll
        for (int nt = 0; nt < 4; nt++) {
            int r0 = mb + wm + mt * 16 + (lane >> 2);
            int cc = hb + wn + nt * 8 + 2 * (lane & 3);
            float* p0 = out + (size_t)r0 * NH + cc;
            float* p1 = out + (size_t)(r0 + 8) * NH + cc;
            atomicAdd(p0,     oacc[mt][nt][0]);
            atomicAdd(p0 + 1, oacc[mt][nt][1]);
            atomicAdd(p1,     oacc[mt][nt][2]);
            atomicAdd(p1 + 1, oacc[mt][nt][3]);
        }
}

// ---------------- launch -----------------------------------------------------
extern "C" void kernel_launch(void* const* d_in, const int* in_sizes, int n_in,
                              void* d_out, int out_size) {
    const float* x       = (const float*)d_in[0];  // [B, D]
    const float* centers = (const float*)d_in[1];  // [E, D]
    const float* W       = (const float*)d_in[2];  // [E, H, D]
    const float* bias    = (const float*)d_in[3];  // [E, H]
    float* out = (float*)d_out;                    // [B, H]

    cudaFuncSetAttribute(gemm_kernel, cudaFuncAttributeMaxDynamicSharedMemorySize, SMEM_TOTAL);

    // 4096 W blocks + 1024 x blocks + 8192 zero blocks
    prep_kernel<<<4096 + 1024 + 8192, 256>>>(x, W, centers, bias, (float4*)out);

    dim3 grid(NH / 128, NB / 128, 2);   // 1024 CTAs
    gemm_kernel<<<grid, 256, SMEM_TOTAL>>>(out);
}

// round 16
// speedup vs baseline: 2.3275x; 1.0097x over previous
#include <cuda_runtime.h>
#include <cuda_fp16.h>
#include <cstdint>

typedef unsigned long long u64;
typedef uint32_t u32;

#define NB 4096
#define NE 16
#define ND 512
#define NH 2048

#define KC 64                          // k-chunk: 64 fp16 = 128B rows
#define TILE 16384                     // 128 x 64 fp16 tile bytes
#define STAGE (2 * TILE)               // x tile + w tile per chunk
#define NSTAGE 6
#define SMEM_TOTAL (NSTAGE * STAGE)    // 196608 B
#define NSM 148
#define NTILES 1024                    // 16 hx * 32 my * 2 z

// ---------------- scratch (device globals; no allocations allowed) ----------
__device__ __half g_xh[NB * ND];
__device__ __half g_wh[NE * NH * ND];
__device__ float  g_dcomb[NE * NH];

// ---------------- PTX helpers ----------------------------------------------
__device__ __forceinline__ u32 smem_u32(const void* p) {
    u32 a;
    asm("{ .reg .u64 t; cvta.to.shared.u64 t, %1; cvt.u32.u64 %0, t; }" : "=r"(a) : "l"(p));
    return a;
}
__device__ __forceinline__ void cp16(u32 dst, const void* src) {
    asm volatile("cp.async.cg.shared.global [%0], [%1], 16;" :: "r"(dst), "l"(src) : "memory");
}
__device__ __forceinline__ void cp_commit() { asm volatile("cp.async.commit_group;" ::: "memory"); }
__device__ __forceinline__ void cp_wait1()  { asm volatile("cp.async.wait_group 1;" ::: "memory"); }

__device__ __forceinline__ void ldsm4(u32& r0, u32& r1, u32& r2, u32& r3, u32 addr) {
    asm volatile("ldmatrix.sync.aligned.m8n8.x4.shared.b16 {%0,%1,%2,%3}, [%4];"
                 : "=r"(r0), "=r"(r1), "=r"(r2), "=r"(r3) : "r"(addr));
}
__device__ __forceinline__ void mma16816(float* c, const u32* a, const u32* b) {
    asm volatile("mma.sync.aligned.m16n8k16.row.col.f32.f16.f16.f32 "
                 "{%0,%1,%2,%3}, {%4,%5,%6,%7}, {%8,%9}, {%0,%1,%2,%3};"
                 : "+f"(c[0]), "+f"(c[1]), "+f"(c[2]), "+f"(c[3])
                 : "r"(a[0]), "r"(a[1]), "r"(a[2]), "r"(a[3]), "r"(b[0]), "r"(b[1]));
}

__device__ __forceinline__ u32 swz128(u32 off) { return off ^ ((off >> 3) & 0x70); }

__device__ __forceinline__ u32 h2u(__half2 h) { return *(u32*)&h; }

// ---------------- fused prep + zero kernel -----------------------------------
// blocks [0, 4096):      W rows -> fp16 (16B stores) + d = bias - c_e.W_row
// blocks [4096, 5120):   x -> fp16 (16B stores)
// blocks [5120, 13312):  zero out
__global__ void prep_kernel(const float* __restrict__ x,
                            const float* __restrict__ W,
                            const float* __restrict__ centers,
                            const float* __restrict__ bias,
                            float4* __restrict__ out) {
    int b = blockIdx.x;
    if (b < 4096) {
        int gw   = b * 8 + (threadIdx.x >> 5);
        int lane = threadIdx.x & 31;
        int e = gw >> 11;
        const float4* wr = (const float4*)(W + (size_t)gw * ND);
        const float4* cr = (const float4*)(centers + (size_t)e * ND);
        uint4* ph = (uint4*)(g_wh + (size_t)gw * ND);
        float s = 0.f;
#pragma unroll
        for (int i = 0; i < 2; i++) {
            int q = lane + 32 * i;          // uint4 (8-half) index, 0..63
            float4 wa = wr[2 * q], wb = wr[2 * q + 1];
            float4 ca = cr[2 * q], cb = cr[2 * q + 1];
            s += wa.x * ca.x + wa.y * ca.y + wa.z * ca.z + wa.w * ca.w
               + wb.x * cb.x + wb.y * cb.y + wb.z * cb.z + wb.w * cb.w;
            uint4 h;
            h.x = h2u(__floats2half2_rn(wa.x, wa.y));
            h.y = h2u(__floats2half2_rn(wa.z, wa.w));
            h.z = h2u(__floats2half2_rn(wb.x, wb.y));
            h.w = h2u(__floats2half2_rn(wb.z, wb.w));
            ph[q] = h;
        }
#pragma unroll
        for (int o = 16; o; o >>= 1) s += __shfl_xor_sync(0xffffffffu, s, o);
        if (lane == 0) g_dcomb[gw] = bias[gw] - s;
    } else if (b < 5120) {
        int i = (b - 4096) * 256 + threadIdx.x;   // 8-float group index
        const float4* xr = (const float4*)x;
        float4 a = xr[2 * i], c = xr[2 * i + 1];
        uint4 h;
        h.x = h2u(__floats2half2_rn(a.x, a.y));
        h.y = h2u(__floats2half2_rn(a.z, a.w));
        h.z = h2u(__floats2half2_rn(c.x, c.y));
        h.w = h2u(__floats2half2_rn(c.z, c.w));
        ((uint4*)g_xh)[i] = h;
    } else {
        out[(size_t)(b - 5120) * 256 + threadIdx.x] = make_float4(0.f, 0.f, 0.f, 0.f);
    }
}

// ---------------- main GEMM kernel (persistent) -------------------------------
// grid 148; 256 threads, 8 warps (2m x 4n of 64x32). CTA p processes tiles
// p, p+148, ... of the 1024-tile list (16 hx x 32 my x 2 expert-halves).
// The 6-stage cp.async ring runs CONTINUOUSLY across tile boundaries: pair
// lp consumes chunks 2lp, 2lp+1; prefetch covers pair lp+2 (possibly next
// tile). Epilogue bias loaded straight from L2 one pair early.

__device__ __forceinline__ void tparams(int t, int& mb, int& hb, int& eb) {
    hb = (t & 15) << 7;                // hx * 128
    mb = ((t >> 4) & 31) << 7;         // my * 128
    eb = (t >> 9) << 3;                // z * 8
}

// load chunk k (0/1) of local pair lp; stage ring indexed by global chunk
__device__ __forceinline__ void load_chunk_g(int lp, int k, int first_tile,
                                             u32 sb, int tid) {
    int t = first_tile + NSM * (lp >> 5);
    int mb, hb, eb;
    tparams(t, mb, hb, eb);
    int c = ((lp & 31) << 1) | k;      // chunk within tile, 0..63
    int e = eb + (c >> 3), kc = (c & 7) * KC;
    u32 dst = sb + (u32)((2 * lp + k) % NSTAGE) * STAGE;
    int row = tid >> 3, cc = tid & 7;
    u32 so = swz128((u32)(row * 128 + cc * 16));
    const __half* pxh = g_xh + (size_t)(mb + row) * ND + kc + cc * 8;
    const __half* pwh = g_wh + (size_t)(e * NH + hb + row) * ND + kc + cc * 8;
#pragma unroll
    for (int i = 0; i < 4; i++) {
        u32 d = dst + so + (u32)i * 4096;          // +32 rows per step
        size_t eo = (size_t)(32 * i) * ND;
        cp16(d + 0 * TILE, pxh + eo);
        cp16(d + 1 * TILE, pwh + eo);
    }
}

__device__ __forceinline__ void load_frags(int ks, u32 Ah, u32 Bh, int wm, int wn,
                                           int lane, u32 ah[4][4], u32 bh[4][2]) {
    u32 arel = swz128((u32)((lane & 15) * 128 + ks * 32 + (lane >> 4) * 16));
#pragma unroll
    for (int mt = 0; mt < 4; mt++) {
        u32 ao = (u32)((wm + mt * 16) * 128) + arel;
        ldsm4(ah[mt][0], ah[mt][1], ah[mt][2], ah[mt][3], Ah + ao);
    }
    u32 brel = swz128((u32)((lane & 7) * 128 + ks * 32 + ((lane >> 3) & 1) * 16));
#pragma unroll
    for (int pr = 0; pr < 2; pr++) {
        u32 bo = (u32)((wn + pr * 16 + ((lane >> 4) & 1) * 8) * 128) + brel;
        ldsm4(bh[pr * 2][0], bh[pr * 2][1], bh[pr * 2 + 1][0], bh[pr * 2 + 1][1], Bh + bo);
    }
}

#define MMA_BLOCK(buf)                                                       \
    _Pragma("unroll")                                                        \
    for (int mt = 0; mt < 4; mt++)                                           \
        _Pragma("unroll")                                                    \
        for (int nt = 0; nt < 4; nt++)                                       \
            mma16816(acc[mt][nt], ah[buf][mt], bh[buf][nt]);

__global__ void __launch_bounds__(256, 1)
gemm_kernel(float* __restrict__ out) {
    extern __shared__ char smem[];
    u32 sb = smem_u32(smem);
    const int tid = threadIdx.x, wid = tid >> 5, lane = tid & 31;
    const int wm = (wid >> 2) * 64, wn = (wid & 3) * 32;
    const int first_tile = blockIdx.x;

    const int ntiles = (NTILES - first_tile + NSM - 1) / NSM;   // 6 or 7
    const int total_pairs = ntiles * 32;

    // prologue: pairs 0 and 1 (chunks 0..3), one commit per pair
    load_chunk_g(0, 0, first_tile, sb, tid);
    load_chunk_g(0, 1, first_tile, sb, tid); cp_commit();
    load_chunk_g(1, 0, first_tile, sb, tid);
    load_chunk_g(1, 1, first_tile, sb, tid); cp_commit();

    float acc[4][4][4], oacc[4][4][4];
#pragma unroll
    for (int a = 0; a < 4; a++)
#pragma unroll
        for (int b = 0; b < 4; b++)
#pragma unroll
            for (int c = 0; c < 4; c++) { acc[a][b][c] = 0.f; oacc[a][b][c] = 0.f; }

    u32 ah[2][4][4], bh[2][4][2];
    float2 dreg[4];

    for (int lp = 0; lp < total_pairs; lp++) {
        int mb, hb, eb;
        tparams(first_tile + NSM * (lp >> 5), mb, hb, eb);

        cp_wait1();                    // groups up to G_lp complete
        __syncthreads();

        u32 s0 = sb + (u32)((2 * lp)     % NSTAGE) * STAGE;
        u32 s1 = sb + (u32)((2 * lp + 1) % NSTAGE) * STAGE;
        u32 A0 = s0, B0 = s0 + TILE, A1 = s1, B1 = s1 + TILE;

        // ---- chunk c0, ks0: frags + MMAs FIRST (LDGSTS burst deferred) ----
        load_frags(0, A0, B0, wm, wn, lane, ah[0], bh[0]);
        load_frags(1, A0, B0, wm, wn, lane, ah[1], bh[1]);
        MMA_BLOCK(0)

        // ---- global->smem prefetch for pair lp+2 rides in the MMA shadow ----
        if (lp + 2 < total_pairs) {
            load_chunk_g(lp + 2, 0, first_tile, sb, tid);
            load_chunk_g(lp + 2, 1, first_tile, sb, tid);
        }
        cp_commit();

        // prefetch the epilogue bias one pair early (L2 hit, off critical path)
        if ((lp & 3) == 2) {
            const float2* dp = (const float2*)
                (g_dcomb + (size_t)(eb + ((lp & 31) >> 2)) * NH + hb + wn);
#pragma unroll
            for (int nt = 0; nt < 4; nt++) dreg[nt] = dp[nt * 4 + (lane & 3)];
        }

        // ---- chunk c0, ks1..3 (at ks3 preload chunk c1's ks0) ----
        load_frags(2, A0, B0, wm, wn, lane, ah[0], bh[0]);
        MMA_BLOCK(1)
        load_frags(3, A0, B0, wm, wn, lane, ah[1], bh[1]);
        MMA_BLOCK(0)
        load_frags(0, A1, B1, wm, wn, lane, ah[0], bh[0]);
        MMA_BLOCK(1)

        // ---- chunk c1 ----
#pragma unroll
        for (int ks = 0; ks < 4; ks++) {
            int cur = ks & 1;
            if (ks < 3) load_frags(ks + 1, A1, B1, wm, wn, lane, ah[cur ^ 1], bh[cur ^ 1]);
            MMA_BLOCK(cur)
        }

        if ((lp & 3) == 3) {           // finished local expert: relu + accumulate
#pragma unroll
            for (int nt = 0; nt < 4; nt++) {
                float2 d2 = dreg[nt];
#pragma unroll
                for (int mt = 0; mt < 4; mt++) {
                    oacc[mt][nt][0] += fmaxf(acc[mt][nt][0] + d2.x, 0.f);
                    oacc[mt][nt][1] += fmaxf(acc[mt][nt][1] + d2.y, 0.f);
                    oacc[mt][nt][2] += fmaxf(acc[mt][nt][2] + d2.x, 0.f);
                    oacc[mt][nt][3] += fmaxf(acc[mt][nt][3] + d2.y, 0.f);
                    acc[mt][nt][0] = 0.f; acc[mt][nt][1] = 0.f;
                    acc[mt][nt][2] = 0.f; acc[mt][nt][3] = 0.f;
                }
            }
        }

        if ((lp & 31) == 31) {         // tile done: accumulate into out, reset
#pragma unroll
            for (int mt = 0; mt < 4; mt++)
#pragma unroll
                for (int nt = 0; nt < 4; nt++) {
                    int r0 = mb + wm + mt * 16 + (lane >> 2);
                    int cc = hb + wn + nt * 8 + 2 * (lane & 3);
                    float* p0 = out + (size_t)r0 * NH + cc;
                    float* p1 = out + (size_t)(r0 + 8) * NH + cc;
                    atomicAdd(p0,     oacc[mt][nt][0]);
                    atomicAdd(p0 + 1, oacc[mt][nt][1]);
                    atomicAdd(p1,     oacc[mt][nt][2]);
                    atomicAdd(p1 + 1, oacc[mt][nt][3]);
                    oacc[mt][nt][0] = 0.f; oacc[mt][nt][1] = 0.f;
                    oacc[mt][nt][2] = 0.f; oacc[mt][nt][3] = 0.f;
                }
        }
    }
}

// ---------------- launch -----------------------------------------------------
extern "C" void kernel_launch(void* const* d_in, const int* in_sizes, int n_in,
                              void* d_out, int out_size) {
    const float* x       = (const float*)d_in[0];  // [B, D]
    const float* centers = (const float*)d_in[1];  // [E, D]
    const float* W       = (const float*)d_in[2];  // [E, H, D]
    const float* bias    = (const float*)d_in[3];  // [E, H]
    float* out = (float*)d_out;                    // [B, H]

    cudaFuncSetAttribute(gemm_kernel, cudaFuncAttributeMaxDynamicSharedMemorySize, SMEM_TOTAL);

    // 4096 W blocks + 1024 x blocks + 8192 zero blocks
    prep_kernel<<<4096 + 1024 + 8192, 256>>>(x, W, centers, bias, (float4*)out);

    gemm_kernel<<<NSM, 256, SMEM_TOTAL>>>(out);
}